// round 4
// baseline (speedup 1.0000x reference)
#include <cuda_runtime.h>
#include <cuda_bf16.h>
#include <cstdint>

#define N_TOKENS 16384
#define HIDDEN   4096
#define NE       192   // 3 * 64 experts
#define E        64
#define LOG2E    1.4426950408889634f

// ---------------- scratch ----------------------------------------------------
__device__ __nv_bfloat16 g_w_hi[NE * HIDDEN];
__device__ __nv_bfloat16 g_w_lo[NE * HIDDEN];

// ---------------- helpers ----------------------------------------------------
__device__ __forceinline__ uint32_t smem_u32(const void* p) {
    uint32_t a;
    asm("{ .reg .u64 t; cvta.to.shared.u64 t, %1; cvt.u32.u64 %0, t; }" : "=r"(a) : "l"(p));
    return a;
}
__device__ __forceinline__ void sts64(uint32_t addr, uint32_t a, uint32_t b) {
    asm volatile("st.shared.v2.b32 [%0], {%1, %2};" :: "r"(addr), "r"(a), "r"(b));
}
__device__ __forceinline__ void cp_async16(uint32_t dst, const void* src) {
    asm volatile("cp.async.cg.shared.global [%0], [%1], 16;" :: "r"(dst), "l"(src));
}
__device__ __forceinline__ void cp_commit() {
    asm volatile("cp.async.commit_group;" ::: "memory");
}
template <int N>
__device__ __forceinline__ void cp_wait() {
    asm volatile("cp.async.wait_group %0;" :: "n"(N) : "memory");
}
__device__ __forceinline__ void ldmatrix_x4(uint32_t* r, uint32_t addr) {
    asm volatile("ldmatrix.sync.aligned.m8n8.x4.shared.b16 {%0,%1,%2,%3}, [%4];"
                 : "=r"(r[0]), "=r"(r[1]), "=r"(r[2]), "=r"(r[3]) : "r"(addr));
}
__device__ __forceinline__ void mma_bf16(float* d, const uint32_t* a, const uint32_t* b) {
    asm volatile(
        "mma.sync.aligned.m16n8k16.row.col.f32.bf16.bf16.f32 "
        "{%0,%1,%2,%3}, {%4,%5,%6,%7}, {%8,%9}, {%0,%1,%2,%3};"
        : "+f"(d[0]), "+f"(d[1]), "+f"(d[2]), "+f"(d[3])
        : "r"(a[0]), "r"(a[1]), "r"(a[2]), "r"(a[3]), "r"(b[0]), "r"(b[1]));
}
__device__ __forceinline__ float ex2_approx(float x) {
    float y;
    asm("ex2.approx.f32 %0, %1;" : "=f"(y) : "f"(x));
    return y;
}
__device__ __forceinline__ uint32_t pack_bf16_hi2(float x0, float x1, uint32_t& lo_out) {
    __nv_bfloat16 h0 = __float2bfloat16(x0);
    __nv_bfloat16 h1 = __float2bfloat16(x1);
    __nv_bfloat16 l0 = __float2bfloat16(x0 - __bfloat162float(h0));
    __nv_bfloat16 l1 = __float2bfloat16(x1 - __bfloat162float(h1));
    lo_out = ((uint32_t)__bfloat16_as_ushort(l1) << 16) | __bfloat16_as_ushort(l0);
    return ((uint32_t)__bfloat16_as_ushort(h1) << 16) | __bfloat16_as_ushort(h0);
}

// ---------------- kernel 1: split W into bf16 hi/lo --------------------------
__global__ void prep_w_kernel(const float* __restrict__ W) {
    int i = blockIdx.x * blockDim.x + threadIdx.x;   // float4 index
    float4 v = reinterpret_cast<const float4*>(W)[i];
    uint32_t l01, l23;
    uint32_t h01 = pack_bf16_hi2(v.x, v.y, l01);
    uint32_t h23 = pack_bf16_hi2(v.z, v.w, l23);
    uint2* hp = reinterpret_cast<uint2*>(g_w_hi);
    uint2* lp = reinterpret_cast<uint2*>(g_w_lo);
    hp[i] = make_uint2(h01, h23);
    lp[i] = make_uint2(l01, l23);
}

// ---------------- fused GEMM + softmax-attention kernel ----------------------
// CTA: 128 tokens x 192 cols, BK=32, 8 warps (4M x 2N), warp tile 32x96.
// SMEM: A 2 stages x 20480 (hi 128x80 + lo 128x80)
//       B 4 stages x 30720 (hi 192x80 + lo 192x80), B via cp.async
// Epilogue reuses stage smem: q2[128][65] f32 + kv[128][66] float2.
static constexpr int BK       = 32;
static constexpr int NSTEP    = HIDDEN / BK;   // 128
static constexpr int A_STAGE  = 20480;
static constexpr int B_OFF    = 2 * A_STAGE;   // 40960
static constexpr int B_STAGE  = 30720;
static constexpr int B_LO_SUB = 15360;
static constexpr int A_LO_SUB = 10240;
static constexpr int GEMM_SMEM = B_OFF + 4 * B_STAGE;  // 163840
static constexpr int Q2_OFF   = 0;                      // 128*65*4 = 33280
static constexpr int KV_OFF   = 33280;                  // 128*66*8 = 67584 (end 100864)

__global__ void __launch_bounds__(256, 1)
gemm_fused_kernel(const float* __restrict__ A, float* __restrict__ out) {
    extern __shared__ char smem[];
    const uint32_t sb  = smem_u32(smem);
    const int tid   = threadIdx.x;
    const int wid   = tid >> 5;
    const int lid   = tid & 31;
    const int mbase = blockIdx.x * 128;
    const int m0    = (wid >> 1) * 32;   // warp M offset
    const int n0    = (wid & 1) * 96;    // warp N offset

    float acc[2][12][4];
    #pragma unroll
    for (int mt = 0; mt < 2; ++mt)
        #pragma unroll
        for (int n = 0; n < 12; ++n)
            #pragma unroll
            for (int j = 0; j < 4; ++j) acc[mt][n][j] = 0.f;

    // ---- A register staging (fp32 -> bf16 split) ----
    const int a_row = tid >> 3, a_q = tid & 7;
    float4 va[4];
    auto g2r_a = [&](int kt) {
        const float4* Ag = reinterpret_cast<const float4*>(
            A + (size_t)mbase * HIDDEN + kt * BK);
        #pragma unroll
        for (int i = 0; i < 4; ++i)
            va[i] = Ag[(size_t)(a_row + i * 32) * (HIDDEN / 4) + a_q];
    };
    auto r2s_a = [&](int kt) {
        const uint32_t st = sb + (kt & 1) * A_STAGE;
        #pragma unroll
        for (int i = 0; i < 4; ++i) {
            uint32_t l01, l23;
            uint32_t h01 = pack_bf16_hi2(va[i].x, va[i].y, l01);
            uint32_t h23 = pack_bf16_hi2(va[i].z, va[i].w, l23);
            uint32_t off = (uint32_t)((a_row + i * 32) * 80 + a_q * 8);
            sts64(st + off, h01, h23);
            sts64(st + A_LO_SUB + off, l01, l23);
        }
    };

    // ---- B cp.async ----
    const int b_r = tid >> 2, b_c = (tid & 3) * 16;
    auto cp_b = [&](int kt) {
        const uint32_t st = sb + B_OFF + (kt & 3) * B_STAGE;
        const char* hp = reinterpret_cast<const char*>(g_w_hi);
        const char* lp = reinterpret_cast<const char*>(g_w_lo);
        #pragma unroll
        for (int i = 0; i < 3; ++i) {
            int r = b_r + i * 64;
            uint32_t doff = (uint32_t)(r * 80 + b_c);
            size_t soff = (size_t)r * (HIDDEN * 2) + kt * (BK * 2) + b_c;
            cp_async16(st + doff, hp + soff);
            cp_async16(st + B_LO_SUB + doff, lp + soff);
        }
    };

    // ---- ldmatrix lane addressing ----
    const uint32_t a_lrow = (uint32_t)(m0 + (lid & 15));
    const uint32_t a_lcol = (uint32_t)(((lid >> 4) & 1) * 16);
    const uint32_t b_lrow = (uint32_t)(n0 + (lid & 7) + ((lid >> 4) & 1) * 8);
    const uint32_t b_lcol = (uint32_t)(((lid >> 3) & 1) * 16);

    auto compute = [&](int kt) {
        const uint32_t aST = sb + (kt & 1) * A_STAGE;
        const uint32_t bST = sb + B_OFF + (kt & 3) * B_STAGE;
        #pragma unroll
        for (int h = 0; h < 2; ++h) {
            uint32_t ah[2][4], al[2][4];
            #pragma unroll
            for (int mt = 0; mt < 2; ++mt) {
                uint32_t aoff = (a_lrow + mt * 16) * 80 + a_lcol + h * 32;
                ldmatrix_x4(ah[mt], aST + aoff);
                ldmatrix_x4(al[mt], aST + A_LO_SUB + aoff);
            }
            #pragma unroll
            for (int n2 = 0; n2 < 6; ++n2) {
                uint32_t bh[4], bl[4];
                uint32_t boff = (b_lrow + n2 * 16) * 80 + b_lcol + h * 32;
                ldmatrix_x4(bh, bST + boff);
                ldmatrix_x4(bl, bST + B_LO_SUB + boff);
                #pragma unroll
                for (int mt = 0; mt < 2; ++mt) {
                    mma_bf16(acc[mt][2 * n2],     ah[mt], bh);
                    mma_bf16(acc[mt][2 * n2],     ah[mt], bl);
                    mma_bf16(acc[mt][2 * n2],     al[mt], bh);
                    mma_bf16(acc[mt][2 * n2 + 1], ah[mt], bh + 2);
                    mma_bf16(acc[mt][2 * n2 + 1], ah[mt], bl + 2);
                    mma_bf16(acc[mt][2 * n2 + 1], al[mt], bh + 2);
                }
            }
        }
    };

    // ---- prologue ----
    cp_b(0); cp_commit();
    cp_b(1); cp_commit();
    cp_b(2); cp_commit();
    g2r_a(0);
    r2s_a(0);
    cp_wait<2>();           // group 0 done
    __syncthreads();

    // ---- mainloop: one sync per k-step ----
    for (int kt = 0; kt < NSTEP; ++kt) {
        if (kt + 3 < NSTEP) { cp_b(kt + 3); cp_commit(); }
        if (kt + 1 < NSTEP) g2r_a(kt + 1);
        compute(kt);
        if (kt + 1 < NSTEP) r2s_a(kt + 1);
        cp_wait<2>();
        __syncthreads();
    }

    // ---- write mix tile into reused smem: q2 (scaled by log2e) + kv pairs ----
    float* q2  = reinterpret_cast<float*>(smem + Q2_OFF);   // [128][65]
    float* kvf = reinterpret_cast<float*>(smem + KV_OFF);   // [128][66] float2
    const int d_row = lid >> 2, d_col = (lid & 3) * 2;
    #pragma unroll
    for (int mt = 0; mt < 2; ++mt) {
        #pragma unroll
        for (int n = 0; n < 12; ++n) {
            int t = m0 + mt * 16 + d_row;
            int c = n0 + n * 8 + d_col;
            #pragma unroll
            for (int j = 0; j < 4; ++j) {
                int tt = t + (j >> 1) * 8;
                int cc = c + (j & 1);
                float v = acc[mt][n][j];
                if (cc < 64)       q2[tt * 65 + cc] = v * LOG2E;
                else if (cc < 128) kvf[(tt * 66 + cc - 64) * 2]      = v;
                else               kvf[(tt * 66 + cc - 128) * 2 + 1] = v;
            }
        }
    }
    __syncthreads();

    // ---- fused epilogue: per-token softmax attention ----
    const int token = tid >> 1;       // 0..127
    const int g     = tid & 1;        // owns 32 experts
    const float2* kvt = reinterpret_cast<const float2*>(kvf) + token * 66;
    const float*  q2t = q2 + token * 65;
    float* outt = out + (size_t)(mbase + token) * E;

    #pragma unroll 1
    for (int ei = 0; ei < 32; ei += 2) {
        int e0 = g * 32 + ei;
        float qa = q2t[e0], qb = q2t[e0 + 1];
        float Za = 0.f, Zb = 0.f, Sa = 0.f, Sb = 0.f;
        #pragma unroll 16
        for (int f = 0; f < E; ++f) {
            float2 p = kvt[f];
            float ta = ex2_approx(qa * p.x);
            float tb = ex2_approx(qb * p.x);
            Za += ta; Sa = fmaf(ta, p.y, Sa);
            Zb += tb; Sb = fmaf(tb, p.y, Sb);
        }
        outt[e0]     = __fdividef(Sa, Za);
        outt[e0 + 1] = __fdividef(Sb, Zb);
    }
}

// ---------------- launch -----------------------------------------------------
extern "C" void kernel_launch(void* const* d_in, const int* in_sizes, int n_in,
                              void* d_out, int out_size) {
    const float* hidden = (const float*)d_in[0];   // [16384, 4096] f32
    const float* W      = (const float*)d_in[1];   // [192, 4096]  f32
    float* out          = (float*)d_out;           // [16384, 64]  f32

    cudaFuncSetAttribute(gemm_fused_kernel,
                         cudaFuncAttributeMaxDynamicSharedMemorySize, GEMM_SMEM);

    prep_w_kernel<<<(NE * HIDDEN / 4) / 256, 256>>>(W);
    gemm_fused_kernel<<<N_TOKENS / 128, 256, GEMM_SMEM>>>(hidden, out);
}

// round 5
// speedup vs baseline: 1.1251x; 1.1251x over previous
#include <cuda_runtime.h>
#include <cuda_bf16.h>
#include <cstdint>

#define N_TOKENS 16384
#define HIDDEN   4096
#define NE       192   // 3 * 64 experts
#define E        64
#define LOG2E    1.4426950408889634f

// ---------------- scratch ----------------------------------------------------
__device__ __nv_bfloat16 g_w_hi[NE * HIDDEN];
__device__ __nv_bfloat16 g_w_lo[NE * HIDDEN];

// ---------------- helpers ----------------------------------------------------
__device__ __forceinline__ uint32_t smem_u32(const void* p) {
    uint32_t a;
    asm("{ .reg .u64 t; cvta.to.shared.u64 t, %1; cvt.u32.u64 %0, t; }" : "=r"(a) : "l"(p));
    return a;
}
__device__ __forceinline__ void sts64(uint32_t addr, uint32_t a, uint32_t b) {
    asm volatile("st.shared.v2.b32 [%0], {%1, %2};" :: "r"(addr), "r"(a), "r"(b));
}
__device__ __forceinline__ void cp_async16(uint32_t dst, const void* src) {
    asm volatile("cp.async.cg.shared.global [%0], [%1], 16;" :: "r"(dst), "l"(src));
}
__device__ __forceinline__ void cp_commit() {
    asm volatile("cp.async.commit_group;" ::: "memory");
}
template <int N>
__device__ __forceinline__ void cp_wait() {
    asm volatile("cp.async.wait_group %0;" :: "n"(N) : "memory");
}
__device__ __forceinline__ void ldmatrix_x4(uint32_t* r, uint32_t addr) {
    asm volatile("ldmatrix.sync.aligned.m8n8.x4.shared.b16 {%0,%1,%2,%3}, [%4];"
                 : "=r"(r[0]), "=r"(r[1]), "=r"(r[2]), "=r"(r[3]) : "r"(addr));
}
__device__ __forceinline__ void mma_bf16(float* d, const uint32_t* a, const uint32_t* b) {
    asm volatile(
        "mma.sync.aligned.m16n8k16.row.col.f32.bf16.bf16.f32 "
        "{%0,%1,%2,%3}, {%4,%5,%6,%7}, {%8,%9}, {%0,%1,%2,%3};"
        : "+f"(d[0]), "+f"(d[1]), "+f"(d[2]), "+f"(d[3])
        : "r"(a[0]), "r"(a[1]), "r"(a[2]), "r"(a[3]), "r"(b[0]), "r"(b[1]));
}
__device__ __forceinline__ float ex2_approx(float x) {
    float y;
    asm("ex2.approx.f32 %0, %1;" : "=f"(y) : "f"(x));
    return y;
}
__device__ __forceinline__ uint32_t pack_bf16_hi2(float x0, float x1, uint32_t& lo_out) {
    __nv_bfloat16 h0 = __float2bfloat16(x0);
    __nv_bfloat16 h1 = __float2bfloat16(x1);
    __nv_bfloat16 l0 = __float2bfloat16(x0 - __bfloat162float(h0));
    __nv_bfloat16 l1 = __float2bfloat16(x1 - __bfloat162float(h1));
    lo_out = ((uint32_t)__bfloat16_as_ushort(l1) << 16) | __bfloat16_as_ushort(l0);
    return ((uint32_t)__bfloat16_as_ushort(h1) << 16) | __bfloat16_as_ushort(h0);
}

// ---------------- kernel 1: split W into bf16 hi/lo --------------------------
__global__ void prep_w_kernel(const float* __restrict__ W) {
    int i = blockIdx.x * blockDim.x + threadIdx.x;   // float4 index
    float4 v = reinterpret_cast<const float4*>(W)[i];
    uint32_t l01, l23;
    uint32_t h01 = pack_bf16_hi2(v.x, v.y, l01);
    uint32_t h23 = pack_bf16_hi2(v.z, v.w, l23);
    reinterpret_cast<uint2*>(g_w_hi)[i] = make_uint2(h01, h23);
    reinterpret_cast<uint2*>(g_w_lo)[i] = make_uint2(l01, l23);
}

// ---------------- fused GEMM + softmax-attention kernel ----------------------
// CTA: 128 tokens x 192 cols, BK=32, 512 threads = 16 warps (4M x 4N),
// warp tile 32x48. SMEM: A 2 stages x 20480, B 4 stages x 30720 (cp.async).
// Epilogue reuses stage smem: q2[128][65] f32 + kv[128][66] float2.
static constexpr int BK        = 32;
static constexpr int NSTEP     = HIDDEN / BK;   // 128
static constexpr int A_STAGE   = 20480;
static constexpr int A_LO_SUB  = 10240;
static constexpr int B_OFF     = 2 * A_STAGE;   // 40960
static constexpr int B_STAGE   = 30720;
static constexpr int B_LO_SUB  = 15360;
static constexpr int GEMM_SMEM = B_OFF + 4 * B_STAGE;  // 163840
static constexpr int Q2_OFF    = 0;                     // 128*65*4 = 33280
static constexpr int KV_OFF    = 33280;                 // 128*66*8 = 67584

__global__ void __launch_bounds__(512, 1)
gemm_fused_kernel(const float* __restrict__ A, float* __restrict__ out) {
    extern __shared__ char smem[];
    const uint32_t sb  = smem_u32(smem);
    const int tid   = threadIdx.x;
    const int wid   = tid >> 5;
    const int lid   = tid & 31;
    const int mbase = blockIdx.x * 128;
    const int m0    = (wid >> 2) * 32;   // warp M offset (4 M-warps)
    const int n0    = (wid & 3) * 48;    // warp N offset (4 N-warps)

    float acc[2][6][4];
    #pragma unroll
    for (int mt = 0; mt < 2; ++mt)
        #pragma unroll
        for (int n = 0; n < 6; ++n)
            #pragma unroll
            for (int j = 0; j < 4; ++j) acc[mt][n][j] = 0.f;

    // ---- A register staging (fp32 -> bf16 split): 2 float4 per thread ----
    const int a_row = tid >> 3, a_q = tid & 7;   // rows a_row, a_row+64
    float4 va[2];
    auto g2r_a = [&](int kt) {
        const float4* Ag = reinterpret_cast<const float4*>(
            A + (size_t)mbase * HIDDEN + kt * BK);
        #pragma unroll
        for (int i = 0; i < 2; ++i)
            va[i] = Ag[(size_t)(a_row + i * 64) * (HIDDEN / 4) + a_q];
    };
    auto r2s_a = [&](int kt) {
        const uint32_t st = sb + (kt & 1) * A_STAGE;
        #pragma unroll
        for (int i = 0; i < 2; ++i) {
            uint32_t l01, l23;
            uint32_t h01 = pack_bf16_hi2(va[i].x, va[i].y, l01);
            uint32_t h23 = pack_bf16_hi2(va[i].z, va[i].w, l23);
            uint32_t off = (uint32_t)((a_row + i * 64) * 80 + a_q * 8);
            sts64(st + off, h01, h23);
            sts64(st + A_LO_SUB + off, l01, l23);
        }
    };

    // ---- B cp.async: 1536 16B chunks per stage, 3 per thread ----
    auto cp_b = [&](int kt) {
        const uint32_t st = sb + B_OFF + (kt & 3) * B_STAGE;
        const char* hp = reinterpret_cast<const char*>(g_w_hi);
        const char* lp = reinterpret_cast<const char*>(g_w_lo);
        #pragma unroll
        for (int i = 0; i < 3; ++i) {
            int idx = tid + i * 512;            // 0..1535
            int half = idx >= 768;              // 0 = hi, 1 = lo
            int j = idx - half * 768;           // 0..767
            int r = j >> 2;                     // row 0..191
            int c = (j & 3) * 16;               // 0,16,32,48
            uint32_t doff = (uint32_t)(r * 80 + c) + (half ? B_LO_SUB : 0u);
            const char* srcb = half ? lp : hp;
            size_t soff = (size_t)r * (HIDDEN * 2) + (size_t)kt * (BK * 2) + c;
            cp_async16(st + doff, srcb + soff);
        }
    };

    // ---- ldmatrix lane addressing ----
    const uint32_t a_lrow = (uint32_t)(m0 + (lid & 15));
    const uint32_t a_lcol = (uint32_t)(((lid >> 4) & 1) * 16);
    const uint32_t b_lrow = (uint32_t)(n0 + (lid & 7) + ((lid >> 4) & 1) * 8);
    const uint32_t b_lcol = (uint32_t)(((lid >> 3) & 1) * 16);

    auto compute = [&](int kt) {
        const uint32_t aST = sb + (kt & 1) * A_STAGE;
        const uint32_t bST = sb + B_OFF + (kt & 3) * B_STAGE;
        #pragma unroll
        for (int h = 0; h < 2; ++h) {
            uint32_t ah[2][4], al[2][4], bh[3][4], bl[3][4];
            #pragma unroll
            for (int mt = 0; mt < 2; ++mt) {
                uint32_t aoff = (a_lrow + mt * 16) * 80 + a_lcol + h * 32;
                ldmatrix_x4(ah[mt], aST + aoff);
                ldmatrix_x4(al[mt], aST + A_LO_SUB + aoff);
            }
            #pragma unroll
            for (int n2 = 0; n2 < 3; ++n2) {
                uint32_t boff = (b_lrow + n2 * 16) * 80 + b_lcol + h * 32;
                ldmatrix_x4(bh[n2], bST + boff);
                ldmatrix_x4(bl[n2], bST + B_LO_SUB + boff);
            }
            // term-major issue: 12 independent accs between reuses
            #pragma unroll
            for (int mt = 0; mt < 2; ++mt)
                #pragma unroll
                for (int n = 0; n < 6; ++n)
                    mma_bf16(acc[mt][n], ah[mt], bh[n >> 1] + (n & 1) * 2);
            #pragma unroll
            for (int mt = 0; mt < 2; ++mt)
                #pragma unroll
                for (int n = 0; n < 6; ++n)
                    mma_bf16(acc[mt][n], ah[mt], bl[n >> 1] + (n & 1) * 2);
            #pragma unroll
            for (int mt = 0; mt < 2; ++mt)
                #pragma unroll
                for (int n = 0; n < 6; ++n)
                    mma_bf16(acc[mt][n], al[mt], bh[n >> 1] + (n & 1) * 2);
        }
    };

    // ---- prologue ----
    cp_b(0); cp_commit();
    cp_b(1); cp_commit();
    cp_b(2); cp_commit();
    g2r_a(0);
    r2s_a(0);
    cp_wait<2>();           // stage 0 ready
    __syncthreads();

    // ---- mainloop ----
    for (int kt = 0; kt < NSTEP; ++kt) {
        if (kt + 3 < NSTEP) { cp_b(kt + 3); cp_commit(); }
        if (kt + 1 < NSTEP) g2r_a(kt + 1);
        compute(kt);
        if (kt + 1 < NSTEP) r2s_a(kt + 1);
        cp_wait<2>();
        __syncthreads();
    }

    // ---- scatter mix tile into reused smem ----
    float* q2  = reinterpret_cast<float*>(smem + Q2_OFF);   // [128][65]
    float* kvf = reinterpret_cast<float*>(smem + KV_OFF);   // [128][66] float2
    const int d_row = lid >> 2, d_col = (lid & 3) * 2;
    #pragma unroll
    for (int mt = 0; mt < 2; ++mt) {
        #pragma unroll
        for (int n = 0; n < 6; ++n) {
            int t = m0 + mt * 16 + d_row;
            int c = n0 + n * 8 + d_col;
            #pragma unroll
            for (int j = 0; j < 4; ++j) {
                int tt = t + (j >> 1) * 8;
                int cc = c + (j & 1);
                float v = acc[mt][n][j];
                if (cc < 64)       q2[tt * 65 + cc] = v * LOG2E;
                else if (cc < 128) kvf[(tt * 66 + cc - 64) * 2]      = v;
                else               kvf[(tt * 66 + cc - 128) * 2 + 1] = v;
            }
        }
    }
    __syncthreads();

    // ---- fused epilogue: per-token softmax attention (4 threads/token) ----
    const int token = tid >> 2;   // 0..127
    const int g     = tid & 3;    // each owns 16 experts
    const float2* kvt = reinterpret_cast<const float2*>(kvf) + token * 66;
    const float*  q2t = q2 + token * 65;
    float* outt = out + (size_t)(mbase + token) * E;

    #pragma unroll 1
    for (int ei = 0; ei < 16; ei += 2) {
        int e0 = g * 16 + ei;
        float qa = q2t[e0], qb = q2t[e0 + 1];
        float Za = 0.f, Zb = 0.f, Sa = 0.f, Sb = 0.f;
        #pragma unroll 16
        for (int f = 0; f < E; ++f) {
            float2 p = kvt[f];
            float ta = ex2_approx(qa * p.x);
            float tb = ex2_approx(qb * p.x);
            Za += ta; Sa = fmaf(ta, p.y, Sa);
            Zb += tb; Sb = fmaf(tb, p.y, Sb);
        }
        outt[e0]     = __fdividef(Sa, Za);
        outt[e0 + 1] = __fdividef(Sb, Zb);
    }
}

// ---------------- launch -----------------------------------------------------
extern "C" void kernel_launch(void* const* d_in, const int* in_sizes, int n_in,
                              void* d_out, int out_size) {
    const float* hidden = (const float*)d_in[0];   // [16384, 4096] f32
    const float* W      = (const float*)d_in[1];   // [192, 4096]  f32
    float* out          = (float*)d_out;           // [16384, 64]  f32

    cudaFuncSetAttribute(gemm_fused_kernel,
                         cudaFuncAttributeMaxDynamicSharedMemorySize, GEMM_SMEM);

    prep_w_kernel<<<(NE * HIDDEN / 4) / 256, 256>>>(W);
    gemm_fused_kernel<<<N_TOKENS / 128, 512, GEMM_SMEM>>>(hidden, out);
}

// round 6
// speedup vs baseline: 1.2224x; 1.0865x over previous
#include <cuda_runtime.h>
#include <cuda_bf16.h>
#include <cstdint>

#define N_TOKENS 16384
#define HIDDEN   4096
#define NE       192   // 3 * 64 experts
#define E        64
#define LOG2E    1.4426950408889634f

// ---------------- scratch ----------------------------------------------------
__device__ __nv_bfloat16 g_w_hi[NE * HIDDEN];
__device__ __nv_bfloat16 g_w_lo[NE * HIDDEN];

// ---------------- helpers ----------------------------------------------------
__device__ __forceinline__ uint32_t smem_u32(const void* p) {
    uint32_t a;
    asm("{ .reg .u64 t; cvta.to.shared.u64 t, %1; cvt.u32.u64 %0, t; }" : "=r"(a) : "l"(p));
    return a;
}
__device__ __forceinline__ void sts64(uint32_t addr, uint32_t a, uint32_t b) {
    asm volatile("st.shared.v2.b32 [%0], {%1, %2};" :: "r"(addr), "r"(a), "r"(b));
}
__device__ __forceinline__ void cp_async16(uint32_t dst, const void* src) {
    asm volatile("cp.async.cg.shared.global [%0], [%1], 16;" :: "r"(dst), "l"(src));
}
__device__ __forceinline__ void cp_commit() {
    asm volatile("cp.async.commit_group;" ::: "memory");
}
template <int N>
__device__ __forceinline__ void cp_wait() {
    asm volatile("cp.async.wait_group %0;" :: "n"(N) : "memory");
}
__device__ __forceinline__ void ldmatrix_x4(uint32_t* r, uint32_t addr) {
    asm volatile("ldmatrix.sync.aligned.m8n8.x4.shared.b16 {%0,%1,%2,%3}, [%4];"
                 : "=r"(r[0]), "=r"(r[1]), "=r"(r[2]), "=r"(r[3]) : "r"(addr));
}
__device__ __forceinline__ void mma_bf16(float* d, const uint32_t* a, const uint32_t* b) {
    asm volatile(
        "mma.sync.aligned.m16n8k16.row.col.f32.bf16.bf16.f32 "
        "{%0,%1,%2,%3}, {%4,%5,%6,%7}, {%8,%9}, {%0,%1,%2,%3};"
        : "+f"(d[0]), "+f"(d[1]), "+f"(d[2]), "+f"(d[3])
        : "r"(a[0]), "r"(a[1]), "r"(a[2]), "r"(a[3]), "r"(b[0]), "r"(b[1]));
}
__device__ __forceinline__ float ex2_approx(float x) {
    float y;
    asm("ex2.approx.f32 %0, %1;" : "=f"(y) : "f"(x));
    return y;
}
__device__ __forceinline__ uint32_t pack_bf16_hi2(float x0, float x1, uint32_t& lo_out) {
    __nv_bfloat16 h0 = __float2bfloat16(x0);
    __nv_bfloat16 h1 = __float2bfloat16(x1);
    __nv_bfloat16 l0 = __float2bfloat16(x0 - __bfloat162float(h0));
    __nv_bfloat16 l1 = __float2bfloat16(x1 - __bfloat162float(h1));
    lo_out = ((uint32_t)__bfloat16_as_ushort(l1) << 16) | __bfloat16_as_ushort(l0);
    return ((uint32_t)__bfloat16_as_ushort(h1) << 16) | __bfloat16_as_ushort(h0);
}
// SW128-style XOR swizzle for 128B-pitch rows (conflict-free ldmatrix):
// works for any 8B-aligned cbyte (XOR only touches bits 4-6).
__device__ __forceinline__ uint32_t swz(uint32_t r, uint32_t cbyte) {
    return r * 128 + (cbyte ^ ((r & 7) << 4));
}

// ---------------- kernel 1: split W into bf16 hi/lo --------------------------
__global__ void prep_w_kernel(const float* __restrict__ W) {
    int i = blockIdx.x * blockDim.x + threadIdx.x;   // float4 index
    float4 v = reinterpret_cast<const float4*>(W)[i];
    uint32_t l01, l23;
    uint32_t h01 = pack_bf16_hi2(v.x, v.y, l01);
    uint32_t h23 = pack_bf16_hi2(v.z, v.w, l23);
    reinterpret_cast<uint2*>(g_w_hi)[i] = make_uint2(h01, h23);
    reinterpret_cast<uint2*>(g_w_lo)[i] = make_uint2(l01, l23);
}

// ---------------- fused GEMM + softmax-attention kernel ----------------------
// CTA: 128 tokens x 192 cols, BK=64, 512 threads = 16 warps (4M x 4N),
// warp tile 32x48. A: 2 stages (hi+lo, swizzled 128B rows). B: 3 stages cp.async.
static constexpr int BK        = 64;
static constexpr int NSTEP     = HIDDEN / BK;     // 64
static constexpr int A_HALF    = 128 * 128;       // 16384 (one of hi/lo)
static constexpr int A_STAGE   = 2 * A_HALF;      // 32768
static constexpr int A_LO_SUB  = A_HALF;
static constexpr int B_OFF     = 2 * A_STAGE;     // 65536
static constexpr int B_HALF    = 192 * 128;       // 24576
static constexpr int B_STAGE   = 2 * B_HALF;      // 49152
static constexpr int B_LO_SUB  = B_HALF;
static constexpr int GEMM_SMEM = B_OFF + 3 * B_STAGE;  // 212992
static constexpr int Q2_OFF    = 0;                     // 128*65*4 = 33280
static constexpr int KV_OFF    = 33280;                 // 128*66*8 = 67584

__global__ void __launch_bounds__(512, 1)
gemm_fused_kernel(const float* __restrict__ A, float* __restrict__ out) {
    extern __shared__ char smem[];
    const uint32_t sb  = smem_u32(smem);
    const int tid   = threadIdx.x;
    const int wid   = tid >> 5;
    const int lid   = tid & 31;
    const int mbase = blockIdx.x * 128;
    const int m0    = (wid >> 2) * 32;   // warp M offset (4 M-warps)
    const int n0    = (wid & 3) * 48;    // warp N offset (4 N-warps)

    float acc[2][6][4];
    #pragma unroll
    for (int mt = 0; mt < 2; ++mt)
        #pragma unroll
        for (int n = 0; n < 6; ++n)
            #pragma unroll
            for (int j = 0; j < 4; ++j) acc[mt][n][j] = 0.f;

    // ---- A register staging: 4 float4 per thread (row tid>>2, 16 f32) ----
    const int a_row = tid >> 2, a_q = tid & 3;
    float4 va[4];
    auto g2r_a = [&](int kt) {
        const float4* Ag = reinterpret_cast<const float4*>(A) +
                           (size_t)(mbase + a_row) * (HIDDEN / 4) + kt * 16;
        #pragma unroll
        for (int i = 0; i < 4; ++i)
            va[i] = Ag[a_q + i * 4];
    };
    auto r2s_a = [&](int kt) {
        const uint32_t st = sb + (kt & 1) * A_STAGE;
        #pragma unroll
        for (int i = 0; i < 4; ++i) {
            uint32_t l01, l23;
            uint32_t h01 = pack_bf16_hi2(va[i].x, va[i].y, l01);
            uint32_t h23 = pack_bf16_hi2(va[i].z, va[i].w, l23);
            uint32_t off = swz((uint32_t)a_row, (uint32_t)(a_q + i * 4) * 8);
            sts64(st + off, h01, h23);
            sts64(st + A_LO_SUB + off, l01, l23);
        }
    };

    // ---- B cp.async: 3072 16B chunks per stage, 6 per thread ----
    auto cp_b = [&](int kt) {
        const uint32_t st = sb + B_OFF + (kt % 3) * B_STAGE;
        const char* hp = reinterpret_cast<const char*>(g_w_hi);
        const char* lp = reinterpret_cast<const char*>(g_w_lo);
        #pragma unroll
        for (int i = 0; i < 6; ++i) {
            int idx = tid + i * 512;          // 0..3071
            int half = idx >= 1536;           // 0 = hi, 1 = lo
            int j = idx - half * 1536;        // 0..1535
            int r = j >> 3;                   // row 0..191
            uint32_t cbyte = (uint32_t)(j & 7) * 16;
            uint32_t dst = st + (half ? B_LO_SUB : 0u) + swz((uint32_t)r, cbyte);
            const char* srcb = half ? lp : hp;
            size_t soff = (size_t)r * (HIDDEN * 2) + (size_t)kt * (BK * 2) + cbyte;
            cp_async16(dst, srcb + soff);
        }
    };

    // ---- ldmatrix lane addressing ----
    const uint32_t a_lrow = (uint32_t)(m0 + (lid & 15));
    const uint32_t a_lcol = (uint32_t)(((lid >> 4) & 1) * 16);
    const uint32_t b_lrow = (uint32_t)(n0 + (lid & 7) + ((lid >> 4) & 1) * 8);
    const uint32_t b_lcol = (uint32_t)(((lid >> 3) & 1) * 16);

    auto compute = [&](int kt) {
        const uint32_t aST = sb + (kt & 1) * A_STAGE;
        const uint32_t bST = sb + B_OFF + (kt % 3) * B_STAGE;
        #pragma unroll
        for (int h = 0; h < 4; ++h) {   // four k16 halves of BK=64
            uint32_t ah[2][4], al[2][4], bh[3][4], bl[3][4];
            #pragma unroll
            for (int mt = 0; mt < 2; ++mt) {
                uint32_t off = swz(a_lrow + mt * 16, a_lcol + h * 32);
                ldmatrix_x4(ah[mt], aST + off);
                ldmatrix_x4(al[mt], aST + A_LO_SUB + off);
            }
            #pragma unroll
            for (int n2 = 0; n2 < 3; ++n2) {
                uint32_t off = swz(b_lrow + n2 * 16, b_lcol + h * 32);
                ldmatrix_x4(bh[n2], bST + off);
                ldmatrix_x4(bl[n2], bST + B_LO_SUB + off);
            }
            // term-major: 12 independent accumulators between reuses
            #pragma unroll
            for (int mt = 0; mt < 2; ++mt)
                #pragma unroll
                for (int n = 0; n < 6; ++n)
                    mma_bf16(acc[mt][n], ah[mt], bh[n >> 1] + (n & 1) * 2);
            #pragma unroll
            for (int mt = 0; mt < 2; ++mt)
                #pragma unroll
                for (int n = 0; n < 6; ++n)
                    mma_bf16(acc[mt][n], ah[mt], bl[n >> 1] + (n & 1) * 2);
            #pragma unroll
            for (int mt = 0; mt < 2; ++mt)
                #pragma unroll
                for (int n = 0; n < 6; ++n)
                    mma_bf16(acc[mt][n], al[mt], bh[n >> 1] + (n & 1) * 2);
        }
    };

    // ---- prologue ----
    cp_b(0); cp_commit();
    cp_b(1); cp_commit();
    g2r_a(0);
    r2s_a(0);
    cp_wait<1>();           // stage 0 ready
    __syncthreads();

    // ---- mainloop: one barrier per 64-wide k-step ----
    for (int kt = 0; kt < NSTEP; ++kt) {
        if (kt + 2 < NSTEP) { cp_b(kt + 2); cp_commit(); }
        if (kt + 1 < NSTEP) g2r_a(kt + 1);
        compute(kt);
        if (kt + 1 < NSTEP) r2s_a(kt + 1);
        cp_wait<1>();
        __syncthreads();
    }

    // ---- scatter mix tile into reused smem ----
    float* q2  = reinterpret_cast<float*>(smem + Q2_OFF);   // [128][65]
    float* kvf = reinterpret_cast<float*>(smem + KV_OFF);   // [128][66] float2
    const int d_row = lid >> 2, d_col = (lid & 3) * 2;
    #pragma unroll
    for (int mt = 0; mt < 2; ++mt) {
        #pragma unroll
        for (int n = 0; n < 6; ++n) {
            int t = m0 + mt * 16 + d_row;
            int c = n0 + n * 8 + d_col;
            #pragma unroll
            for (int j = 0; j < 4; ++j) {
                int tt = t + (j >> 1) * 8;
                int cc = c + (j & 1);
                float v = acc[mt][n][j];
                if (cc < 64)       q2[tt * 65 + cc] = v * LOG2E;
                else if (cc < 128) kvf[(tt * 66 + cc - 64) * 2]      = v;
                else               kvf[(tt * 66 + cc - 128) * 2 + 1] = v;
            }
        }
    }
    __syncthreads();

    // ---- fused epilogue: per-token softmax attention (4 threads/token) ----
    const int token = tid >> 2;   // 0..127
    const int g     = tid & 3;    // each owns 16 experts
    const float2* kvt = reinterpret_cast<const float2*>(kvf) + token * 66;
    const float*  q2t = q2 + token * 65;
    float* outt = out + (size_t)(mbase + token) * E;

    #pragma unroll 1
    for (int ei = 0; ei < 16; ei += 2) {
        int e0 = g * 16 + ei;
        float qa = q2t[e0], qb = q2t[e0 + 1];
        float Za = 0.f, Zb = 0.f, Sa = 0.f, Sb = 0.f;
        #pragma unroll 16
        for (int f = 0; f < E; ++f) {
            float2 p = kvt[f];
            float ta = ex2_approx(qa * p.x);
            float tb = ex2_approx(qb * p.x);
            Za += ta; Sa = fmaf(ta, p.y, Sa);
            Zb += tb; Sb = fmaf(tb, p.y, Sb);
        }
        outt[e0]     = __fdividef(Sa, Za);
        outt[e0 + 1] = __fdividef(Sb, Zb);
    }
}

// ---------------- launch -----------------------------------------------------
extern "C" void kernel_launch(void* const* d_in, const int* in_sizes, int n_in,
                              void* d_out, int out_size) {
    const float* hidden = (const float*)d_in[0];   // [16384, 4096] f32
    const float* W      = (const float*)d_in[1];   // [192, 4096]  f32
    float* out          = (float*)d_out;           // [16384, 64]  f32

    cudaFuncSetAttribute(gemm_fused_kernel,
                         cudaFuncAttributeMaxDynamicSharedMemorySize, GEMM_SMEM);

    prep_w_kernel<<<(NE * HIDDEN / 4) / 256, 256>>>(W);
    gemm_fused_kernel<<<N_TOKENS / 128, 512, GEMM_SMEM>>>(hidden, out);
}